// round 14
// baseline (speedup 1.0000x reference)
#include <cuda_runtime.h>

// B=8, L=512, K=512, M=N=P=D=64
#define BB 8
#define LL 512
#define KS 512

typedef unsigned long long u64;

__device__ float g_vkc[BB * KS * 64];     // [b][k][n]
__device__ float g_W[BB * LL * KS];       // exp-weights (unnormalized) [b][l][kc]
__device__ float g_sinv[BB * LL];         // 1/rowsum
__device__ float g_tmp[BB * LL * 64];     // [b][l][n]

__device__ __forceinline__ void ffma2(u64& d, u64 a, u64 b) {
    asm("fma.rn.f32x2 %0, %1, %2, %0;" : "+l"(d) : "l"(a), "l"(b));
}
__device__ __forceinline__ u64 pack2(float lo, float hi) {
    u64 r;
    asm("mov.b64 %0, {%1, %2};" : "=l"(r) : "f"(lo), "f"(hi));
    return r;
}
__device__ __forceinline__ void unpack2(u64 a, float& lo, float& hi) {
    asm("mov.b64 {%0, %1}, %2;" : "=f"(lo), "=f"(hi) : "l"(a));
}
__device__ __forceinline__ float hsum2(u64 a) {
    float lo, hi; unpack2(a, lo, hi);
    return lo + hi;
}

// ---------------------------------------------------------------------------
// vkc_kernel: vkc[b,k,n] = sum_p vk[b,k,p,n]*vexp[b,k,p]  (streams vk, 67MB)
//   4-way p-split (R13 proven: DRAM 64%, 13.5us)
// ---------------------------------------------------------------------------
__global__ __launch_bounds__(256)
void vkc_kernel(const float* __restrict__ vk,
                const float* __restrict__ vexp) {
    __shared__ float  se[256];
    __shared__ float4 sred[64];

    const int tid = threadIdx.x;
    const int bk0 = blockIdx.x * 4;
    se[tid] = vexp[(size_t)bk0 * 64 + tid];
    __syncthreads();

    const int n4 = tid & 15;
    const int ph = (tid >> 4) & 3;
    const int lb = tid >> 6;
    const int bk = bk0 + lb;

    const float4* vkp = (const float4*)(vk + (size_t)bk * 4096) + ph * 256 + n4;
    const float* ve = se + lb * 64 + ph * 16;

    float4 acc = make_float4(0.f, 0.f, 0.f, 0.f);
#pragma unroll
    for (int p = 0; p < 16; ++p) {
        float4 v = vkp[p * 16];
        float e  = ve[p];
        acc.x = fmaf(v.x, e, acc.x);
        acc.y = fmaf(v.y, e, acc.y);
        acc.z = fmaf(v.z, e, acc.z);
        acc.w = fmaf(v.w, e, acc.w);
    }
    acc.x += __shfl_xor_sync(0xffffffffu, acc.x, 16);
    acc.y += __shfl_xor_sync(0xffffffffu, acc.y, 16);
    acc.z += __shfl_xor_sync(0xffffffffu, acc.z, 16);
    acc.w += __shfl_xor_sync(0xffffffffu, acc.w, 16);

    const int lane = tid & 31;
    const int ph_hi = (tid >> 5) & 1;
    if (ph_hi == 1 && lane < 16)
        sred[lb * 16 + n4] = acc;
    __syncthreads();
    if (ph_hi == 0 && lane < 16) {
        float4 o = sred[lb * 16 + n4];
        o.x += acc.x; o.y += acc.y; o.z += acc.z; o.w += acc.w;
        ((float4*)g_vkc)[(size_t)bk * 16 + n4] = o;
    }
}

// ---------------------------------------------------------------------------
// scores_kernel (runs on 2nd stream, overlapped with vkc_kernel):
//   per block (b, 32 l's): stage q,k -> scores -> softmax -> g_W + g_sinv
// smem: kst[512*65]=33280 | W[32*512]=16384 | qt2[64*17 u64]=2176 | srow[32]
// ---------------------------------------------------------------------------
#define KST_W 0
#define W_OFF 33280
#define QT_OFF 49664
#define SR_OFF (QT_OFF + 2176)
#define SC_WORDS (SR_OFF + 32)
#define SC_SMEM_BYTES (SC_WORDS * 4)             // 207488

__global__ __launch_bounds__(512, 1)
void scores_kernel(const float* __restrict__ q,
                   const float* __restrict__ k,
                   const float* __restrict__ scale_p) {
    extern __shared__ float sm[];
    float* kst  = sm + KST_W;
    float* W    = sm + W_OFF;
    u64*   qt2  = (u64*)(sm + QT_OFF);
    float* srow = sm + SR_OFF;

    const int tid  = threadIdx.x;
    const int w    = tid >> 5;
    const int lane = tid & 31;
    const int b    = blockIdx.x >> 4;
    const int l0   = (blockIdx.x & 15) << 5;
    const float* qb = q + ((size_t)b * LL + l0) * 64;
    const float* kb = k + (size_t)b * KS * 64;
    const float sc  = scale_p[0];

    // stage q as l-pairs
#pragma unroll
    for (int it = 0; it < 2; ++it) {
        int f  = it * 512 + tid;
        int lp = f >> 6, d = f & 63;
        qt2[d * 17 + lp] = pack2(qb[(2 * lp) * 64 + d], qb[(2 * lp + 1) * 64 + d]);
    }
    // stage k [512 kc][64 d] at pitch 65
#pragma unroll 4
    for (int it = 0; it < 16; ++it) {
        int f4 = it * 512 + tid;
        float4 v = ((const float4*)kb)[f4];
        int kc = f4 >> 4, d4 = (f4 & 15) * 4;
        float* dst = kst + kc * 65 + d4;
        dst[0] = v.x; dst[1] = v.y; dst[2] = v.z; dst[3] = v.w;
    }
    __syncthreads();

    // scores: thread tile 4kc x 8l, FFMA2 over l-pairs
    {
        const int lg  = tid & 3;
        const int kcg = tid >> 2;
        const float* kr = kst + 4 * kcg * 65;

        u64 acc[4][4];
#pragma unroll
        for (int j = 0; j < 4; ++j)
#pragma unroll
            for (int p = 0; p < 4; ++p) acc[j][p] = 0ull;

#pragma unroll 4
        for (int d = 0; d < 64; ++d) {
            float k0 = kr[d];
            float k1 = kr[65 + d];
            float k2 = kr[130 + d];
            float k3 = kr[195 + d];
            u64 K0 = pack2(k0, k0), K1 = pack2(k1, k1);
            u64 K2 = pack2(k2, k2), K3 = pack2(k3, k3);
            const u64* qd = qt2 + d * 17 + 4 * lg;
            u64 q0 = qd[0], q1 = qd[1], q2 = qd[2], q3 = qd[3];
            ffma2(acc[0][0], K0, q0); ffma2(acc[0][1], K0, q1);
            ffma2(acc[0][2], K0, q2); ffma2(acc[0][3], K0, q3);
            ffma2(acc[1][0], K1, q0); ffma2(acc[1][1], K1, q1);
            ffma2(acc[1][2], K1, q2); ffma2(acc[1][3], K1, q3);
            ffma2(acc[2][0], K2, q0); ffma2(acc[2][1], K2, q1);
            ffma2(acc[2][2], K2, q2); ffma2(acc[2][3], K2, q3);
            ffma2(acc[3][0], K3, q0); ffma2(acc[3][1], K3, q1);
            ffma2(acc[3][2], K3, q2); ffma2(acc[3][3], K3, q3);
        }
#pragma unroll
        for (int j = 0; j < 4; ++j)
#pragma unroll
            for (int p = 0; p < 4; ++p) {
                float lo, hi; unpack2(acc[j][p], lo, hi);
                int l  = 8 * lg + 2 * p;
                int kc = 4 * kcg + j;
                W[l * 512 + kc]       = lo * sc;
                W[(l + 1) * 512 + kc] = hi * sc;
            }
    }
    __syncthreads();

    // softmax (unnormalized exp in place; 1/sum stashed)
#pragma unroll
    for (int r = 0; r < 2; ++r) {
        int l = w * 2 + r;
        float* Sr = W + l * 512;
        float m = -1e30f;
#pragma unroll
        for (int i = 0; i < 16; ++i) m = fmaxf(m, Sr[lane + 32 * i]);
#pragma unroll
        for (int o = 16; o > 0; o >>= 1)
            m = fmaxf(m, __shfl_xor_sync(0xffffffffu, m, o));
        float s = 0.f;
#pragma unroll
        for (int i = 0; i < 16; ++i) {
            float e = __expf(Sr[lane + 32 * i] - m);
            Sr[lane + 32 * i] = e;
            s += e;
        }
#pragma unroll
        for (int o = 16; o > 0; o >>= 1)
            s += __shfl_xor_sync(0xffffffffu, s, o);
        if (lane == 0) srow[l] = 1.f / s;
    }
    __syncthreads();

    // write W tile + sinv (coalesced float4; rows contiguous in g_W)
    {
        float4* gW4 = (float4*)(g_W + ((size_t)b * LL + l0) * KS);
#pragma unroll
        for (int it = 0; it < 8; ++it)
            gW4[it * 512 + tid] = ((const float4*)W)[it * 512 + tid];
        if (tid < 32)
            g_sinv[(size_t)b * LL + l0 + tid] = srow[tid];
    }
}

// ---------------------------------------------------------------------------
// tmp_kernel: per block (b, 32 l's): tmp = softmax(W) @ vkc  -> g_tmp
// smem: vkc[512*64]=32768 | W[32*512]=16384 | srow[32]
// ---------------------------------------------------------------------------
#define T_VK 0
#define T_W  32768
#define T_SR (32768 + 16384)                     // 49152
#define T_WORDS (T_SR + 32)
#define T_SMEM_BYTES (T_WORDS * 4)               // 196736

__global__ __launch_bounds__(512, 1)
void tmp_kernel() {
    extern __shared__ float sm[];
    float* vkb  = sm + T_VK;                     // [512 kc][64 n]
    float* W    = sm + T_W;                      // [32 l][512 kc]
    float* srow = sm + T_SR;

    const int tid  = threadIdx.x;
    const int w    = tid >> 5;
    const int lane = tid & 31;
    const int b    = blockIdx.x >> 4;
    const int l0   = (blockIdx.x & 15) << 5;

    // loads (W tile is L2-hot from scores_kernel; vkc from vkc_kernel)
    {
        const float4* gW4 = (const float4*)(g_W + ((size_t)b * LL + l0) * KS);
#pragma unroll
        for (int it = 0; it < 8; ++it)
            ((float4*)W)[it * 512 + tid] = gW4[it * 512 + tid];
        const float4* gv4 = (const float4*)(g_vkc + (size_t)b * KS * 64);
#pragma unroll 4
        for (int it = 0; it < 16; ++it)
            ((float4*)vkb)[it * 512 + tid] = gv4[it * 512 + tid];
        if (tid < 32)
            srow[tid] = g_sinv[(size_t)b * LL + l0 + tid];
    }
    __syncthreads();

    // tmp: 4-way kc split, tile 8l x 2n, FFMA2 over kc-pairs (R13 proven)
    const int kcs = w & 3;
    const int wq  = w >> 2;
    {
        u64 acc[8][2];
#pragma unroll
        for (int j = 0; j < 8; ++j) { acc[j][0] = 0ull; acc[j][1] = 0ull; }

        const float* vb = vkb + 2 * lane;
        const float* Wb = W + (8 * wq) * 512;
#pragma unroll 2
        for (int kk = 0; kk < 32; ++kk) {
            int kc = 128 * kcs + 4 * kk;
            const float* vr = vb + kc * 64;
            float2 va = *(const float2*)(vr);
            float2 vb2 = *(const float2*)(vr + 64);
            float2 vc = *(const float2*)(vr + 128);
            float2 vd = *(const float2*)(vr + 192);
            u64 A0 = pack2(va.x, vb2.x), A1 = pack2(va.y, vb2.y);
            u64 B0 = pack2(vc.x, vd.x),  B1 = pack2(vc.y, vd.y);
#pragma unroll
            for (int j = 0; j < 8; ++j) {
                float4 wv = *(const float4*)(Wb + j * 512 + kc);
                u64 w01 = pack2(wv.x, wv.y);
                u64 w23 = pack2(wv.z, wv.w);
                ffma2(acc[j][0], w01, A0); ffma2(acc[j][1], w01, A1);
                ffma2(acc[j][0], w23, B0); ffma2(acc[j][1], w23, B1);
            }
        }
        __syncthreads();                         // W reads done; reuse for P

        float* P = W + kcs * 2048;
#pragma unroll
        for (int j = 0; j < 8; ++j) {
            int l = 8 * wq + j;
            *(float2*)(P + l * 64 + 2 * lane) =
                make_float2(hsum2(acc[j][0]), hsum2(acc[j][1]));
        }
    }
    __syncthreads();

    {
        int idx = tid * 4;
        int l   = idx >> 6;
        float4 s0 = *(const float4*)(W + idx);
        float4 s1 = *(const float4*)(W + 2048 + idx);
        float4 s2 = *(const float4*)(W + 4096 + idx);
        float4 s3 = *(const float4*)(W + 6144 + idx);
        float inv = srow[l];
        float4 o;
        o.x = (s0.x + s1.x + s2.x + s3.x) * inv;
        o.y = (s0.y + s1.y + s2.y + s3.y) * inv;
        o.z = (s0.z + s1.z + s2.z + s3.z) * inv;
        o.w = (s0.w + s1.w + s2.w + s3.w) * inv;
        *(float4*)(g_tmp + ((size_t)b * LL + l0) * 64 + idx) = o;
    }
}

// ---------------------------------------------------------------------------
// out_kernel: per (b,l): attn = vq @ tmp; out = LayerNorm(q + attn)
// ---------------------------------------------------------------------------
__global__ __launch_bounds__(256)
void out_kernel(const float* __restrict__ q,
                const float* __restrict__ vq,
                const float* __restrict__ gamma,
                const float* __restrict__ beta,
                float* __restrict__ out) {
    __shared__ float stmp[64];
    __shared__ float sq[64];
    __shared__ float sy[64];
    __shared__ float red[4];

    const int tid = threadIdx.x;
    const int bl  = blockIdx.x;
    if (tid < 64) {
        stmp[tid] = g_tmp[(size_t)bl * 64 + tid];
        sq[tid]   = q[(size_t)bl * 64 + tid];
    }
    __syncthreads();

    const int m    = tid >> 2;
    const int part = tid & 3;
    const float4* vr = (const float4*)(vq + (size_t)bl * 4096 + m * 64) + part * 4;
    float acc = 0.f;
#pragma unroll
    for (int i = 0; i < 4; ++i) {
        float4 v = vr[i];
        const float* tp = stmp + part * 16 + i * 4;
        acc = fmaf(v.x, tp[0],
              fmaf(v.y, tp[1],
              fmaf(v.z, tp[2],
              fmaf(v.w, tp[3], acc))));
    }
    acc += __shfl_xor_sync(0xffffffffu, acc, 1);
    acc += __shfl_xor_sync(0xffffffffu, acc, 2);
    if (part == 0) sy[m] = sq[m] + acc;
    __syncthreads();

    float y = 0.f;
    if (tid < 64) {
        y = sy[tid];
        float s1 = y;
#pragma unroll
        for (int o = 16; o > 0; o >>= 1)
            s1 += __shfl_xor_sync(0xffffffffu, s1, o);
        if ((tid & 31) == 0) red[tid >> 5] = s1;
    }
    __syncthreads();
    float mu = (red[0] + red[1]) * (1.f / 64.f);
    if (tid < 64) {
        float d = y - mu;
        float s2 = d * d;
#pragma unroll
        for (int o = 16; o > 0; o >>= 1)
            s2 += __shfl_xor_sync(0xffffffffu, s2, o);
        if ((tid & 31) == 0) red[2 + (tid >> 5)] = s2;
    }
    __syncthreads();
    if (tid < 64) {
        float var = (red[2] + red[3]) * (1.f / 64.f);
        float r = rsqrtf(var + 1e-3f);
        out[(size_t)bl * 64 + tid] =
            (y - mu) * r * __ldg(gamma + tid) + __ldg(beta + tid);
    }
}

// ---------------------------------------------------------------------------
extern "C" void kernel_launch(void* const* d_in, const int* in_sizes, int n_in,
                              void* d_out, int out_size) {
    (void)in_sizes; (void)n_in; (void)out_size;
    const float* q     = (const float*)d_in[0];
    const float* k     = (const float*)d_in[1];
    const float* vq    = (const float*)d_in[2];
    const float* vk    = (const float*)d_in[3];
    const float* vexp  = (const float*)d_in[4];
    const float* scale = (const float*)d_in[5];
    const float* gamma = (const float*)d_in[6];
    const float* beta  = (const float*)d_in[7];
    float* out = (float*)d_out;

    // One-time setup (before the first capture call; no device allocations).
    static cudaStream_t s2 = nullptr;
    static cudaEvent_t evFork = nullptr, evJoin = nullptr;
    if (s2 == nullptr) {
        cudaStreamCreateWithFlags(&s2, cudaStreamNonBlocking);
        cudaEventCreateWithFlags(&evFork, cudaEventDisableTiming);
        cudaEventCreateWithFlags(&evJoin, cudaEventDisableTiming);
        cudaFuncSetAttribute(scores_kernel,
                             cudaFuncAttributeMaxDynamicSharedMemorySize,
                             SC_SMEM_BYTES);
        cudaFuncSetAttribute(tmp_kernel,
                             cudaFuncAttributeMaxDynamicSharedMemorySize,
                             T_SMEM_BYTES);
    }

    // Fork: scores (FMA-bound) on s2 overlaps vkc (DRAM-bound) on stream 0.
    cudaEventRecord(evFork, 0);
    cudaStreamWaitEvent(s2, evFork, 0);

    scores_kernel<<<BB * (LL / 32), 512, SC_SMEM_BYTES, s2>>>(q, k, scale);
    vkc_kernel<<<BB * KS / 4, 256>>>(vk, vexp);

    cudaEventRecord(evJoin, s2);
    cudaStreamWaitEvent(0, evJoin, 0);

    tmp_kernel<<<BB * (LL / 32), 512, T_SMEM_BYTES>>>();
    out_kernel<<<BB * LL, 256>>>(q, vq, gamma, beta, out);
}